// round 3
// baseline (speedup 1.0000x reference)
#include <cuda_runtime.h>
#include <cuda_bf16.h>
#include <math.h>

// ---------------- problem constants ----------------
#define BB    32
#define LL    1024
#define CIN   32
#define DM    512
#define NMARK 4
#define GG    4
#define DG    128
#define DIN   256
#define NST   16
#define DTR   8
#define PATCH 16
#define PRED  96
#define NTOK  (BB*PRED)      // 3072 tokens actually needed
#define NEXT  98             // extended token set per batch: l=0 and l=927..1023
#define KE    112            // embed K padded to multiple of 16 (100 -> 112)
#define LN1E4 9.210340371976184f

// ---------------- scratch (static __device__, no allocs) ----------------
__device__ float d_mean [BB*CIN];
__device__ float d_std  [BB*CIN];
__device__ float d_We   [DM*KE];               // fused embed weight, [DM][KE] (cols 100..111 zero)
__device__ float d_pe   [NEXT*DM];             // positional embeds for the 98 needed l values
__device__ float d_A1   [BB*NEXT*KE];          // embed input rows for e1/scale
__device__ float d_e1   [BB*NEXT*DM];
__device__ float d_scale[BB*NEXT*CIN];
__device__ float d_A2   [NTOK*KE];             // embed input rows for xc
__device__ float d_xc   [NTOK*DM];
__device__ float d_xz   [NTOK*2048];           // in_proj output (per group: xc|z)
__device__ float d_xconv[GG*NTOK*DIN];         // silu(depthwise conv)
__device__ float d_dbl  [GG*NTOK*40];          // x_proj output (dt_raw|B|C)
__device__ float d_y    [GG*NTOK*DIN];         // scan output * silu(z)
__device__ float d_xm   [NTOK*DM];             // out_proj output

// ---------------- 1: per-(b,c) mean/std over L ----------------
__global__ void stats_kernel(const float* __restrict__ x_enc) {
    int bc = blockIdx.x;                       // b*32 + c
    const float* xp = x_enc + (size_t)(bc >> 5) * (LL*CIN) + (bc & 31);
    float s = 0.f, sq = 0.f;
    for (int l = threadIdx.x; l < LL; l += 256) {
        float v = xp[(size_t)l * CIN];
        s += v; sq += v * v;
    }
    __shared__ float sh[512];
    sh[threadIdx.x] = s; sh[256 + threadIdx.x] = sq;
    __syncthreads();
    for (int st = 128; st; st >>= 1) {
        if (threadIdx.x < st) {
            sh[threadIdx.x]       += sh[threadIdx.x + st];
            sh[256 + threadIdx.x] += sh[256 + threadIdx.x + st];
        }
        __syncthreads();
    }
    if (threadIdx.x == 0) {
        float m   = sh[0]   * (1.f / LL);
        float var = sh[256] * (1.f / LL) - m * m;
        d_mean[bc] = m;
        d_std[bc]  = sqrtf(var + 1e-5f);
    }
}

// ---------------- 2: build We^T ([DM][KE], zero-padded) + pe table (98x512) ---
__global__ void prep_kernel(const float* __restrict__ conv_w,
                            const float* __restrict__ temp_w) {
    int idx = blockIdx.x * blockDim.x + threadIdx.x;
    if (idx < DM * KE) {
        int d = idx / KE, r = idx % KE;
        float v = 0.f;
        if (r < 96)       v = conv_w[d * 96 + (r & 31) * 3 + (r >> 5)];
        else if (r < 100) v = temp_w[d * 4 + (r - 96)];
        d_We[idx] = v;                          // d_We[d][r]
    } else if (idx < DM * KE + NEXT * DM) {
        int j = idx - DM * KE;
        int u = j / DM, d = j % DM;
        int l = (u == 0) ? 0 : (926 + u);
        float freq = expf(-(float)(d & ~1) * (LN1E4 / (float)DM));
        float arg  = (float)l * freq;
        d_pe[j] = (d & 1) ? cosf(arg) : sinf(arg);
    }
}

// ---------------- 3a: build A1 rows (normalized window + mark) ----------------
__global__ void inv1_kernel(const float* __restrict__ x_enc,
                            const float* __restrict__ mark) {
    int row = blockIdx.x;                      // b*NEXT + u
    int tid = threadIdx.x;
    if (tid >= KE) return;
    int u = row % NEXT, b = row / NEXT;
    int l  = (u == 0) ? 0 : (926 + u);
    int lp = (l == 0) ? (LL - 1) : (l - 1);
    int ln = (l == LL - 1) ? 0 : (l + 1);
    float v = 0.f;
    if (tid < 96) {
        int k = tid >> 5, c = tid & 31;
        int ll = (k == 0) ? lp : ((k == 1) ? l : ln);
        float x = x_enc[((size_t)b * LL + ll) * CIN + c];
        v = (x - d_mean[b * CIN + c]) / d_std[b * CIN + c];
    } else if (tid < 100) {
        v = mark[((size_t)b * LL + l) * NMARK + (tid - 96)];
    }
    d_A1[(size_t)row * KE + tid] = v;
}

// ---------------- 3b: build A2 rows (normalized*(1+scale) + 2*mark) -----------
__global__ void inv2_kernel(const float* __restrict__ x_enc,
                            const float* __restrict__ mark) {
    int row = blockIdx.x;                      // tok = b*96 + j
    int tid = threadIdx.x;
    if (tid >= KE) return;
    int b = row / PRED, j = row % PRED;
    int l  = 928 + j;
    int lp = l - 1;
    int ln = (l == LL - 1) ? 0 : (l + 1);
    float v = 0.f;
    if (tid < 96) {
        int k = tid >> 5, c = tid & 31;
        int ll = (k == 0) ? lp : ((k == 1) ? l : ln);
        int u  = (ll == 0) ? 0 : (ll - 926);
        float x  = x_enc[((size_t)b * LL + ll) * CIN + c];
        float xn = (x - d_mean[b * CIN + c]) / d_std[b * CIN + c];
        v = xn * (1.0f + d_scale[((size_t)b * NEXT + u) * CIN + c]);
    } else if (tid < 100) {
        v = 2.0f * mark[((size_t)b * LL + l) * NMARK + (tid - 96)];
    }
    d_A2[(size_t)row * KE + tid] = v;
}

// =====================================================================
// Big GEMM: 128x128 tile, 8x8 per thread, BK=16, double-buffered smem.
// C[M,N] = A[M,K] @ W[N,K]^T.  Requires K%16==0, N%128==0, lda/ldw%4==0.
// Handles ragged M (guards). EPI: 0=none 1=+pe[m%NEXT] 2=+2*pe[m%96+2]
// =====================================================================
template<int EPI>
__global__ void __launch_bounds__(256, 2)
gemm128(const float* __restrict__ A, const float* __restrict__ W,
        float* __restrict__ C, int M, int N, int K,
        int lda, int ldw, int ldc, long sA, long sW, long sC) {
    int g = blockIdx.z;
    A += (long)g * sA; W += (long)g * sW; C += (long)g * sC;

    __shared__ __align__(16) float As[2][16][132];
    __shared__ __align__(16) float Ws[2][16][132];

    const int tid = threadIdx.x;
    const int tx = tid & 15, ty = tid >> 4;
    const int m0 = blockIdx.y * 128, n0 = blockIdx.x * 128;

    const int lr = tid >> 2;             // 0..63
    const int lk = (tid & 3) * 4;        // 0,4,8,12

    const bool am0 = (m0 + lr)      < M;
    const bool am1 = (m0 + lr + 64) < M;
    const float* Ap0 = A + (size_t)(am0 ? (m0 + lr)      : 0) * lda + lk;
    const float* Ap1 = A + (size_t)(am1 ? (m0 + lr + 64) : 0) * lda + lk;
    const float* Wp0 = W + (size_t)(n0 + lr)      * ldw + lk;
    const float* Wp1 = W + (size_t)(n0 + lr + 64) * ldw + lk;
    const float4 f4z = make_float4(0.f, 0.f, 0.f, 0.f);

    // preload first k-tile
    {
        float4 a0 = am0 ? *(const float4*)(Ap0) : f4z;
        float4 a1 = am1 ? *(const float4*)(Ap1) : f4z;
        float4 w0 = *(const float4*)(Wp0);
        float4 w1 = *(const float4*)(Wp1);
        As[0][lk+0][lr]    = a0.x; As[0][lk+1][lr]    = a0.y;
        As[0][lk+2][lr]    = a0.z; As[0][lk+3][lr]    = a0.w;
        As[0][lk+0][lr+64] = a1.x; As[0][lk+1][lr+64] = a1.y;
        As[0][lk+2][lr+64] = a1.z; As[0][lk+3][lr+64] = a1.w;
        Ws[0][lk+0][lr]    = w0.x; Ws[0][lk+1][lr]    = w0.y;
        Ws[0][lk+2][lr]    = w0.z; Ws[0][lk+3][lr]    = w0.w;
        Ws[0][lk+0][lr+64] = w1.x; Ws[0][lk+1][lr+64] = w1.y;
        Ws[0][lk+2][lr+64] = w1.z; Ws[0][lk+3][lr+64] = w1.w;
    }
    __syncthreads();

    float acc[8][8] = {};
    int buf = 0;

    for (int k0 = 0; k0 < K; k0 += 16) {
        const bool more = (k0 + 16) < K;
        float4 na0 = f4z, na1 = f4z, nw0 = f4z, nw1 = f4z;
        if (more) {
            na0 = am0 ? *(const float4*)(Ap0 + k0 + 16) : f4z;
            na1 = am1 ? *(const float4*)(Ap1 + k0 + 16) : f4z;
            nw0 = *(const float4*)(Wp0 + k0 + 16);
            nw1 = *(const float4*)(Wp1 + k0 + 16);
        }
        #pragma unroll
        for (int kk = 0; kk < 16; kk++) {
            float4 af0 = *(const float4*)&As[buf][kk][ty * 8];
            float4 af1 = *(const float4*)&As[buf][kk][ty * 8 + 4];
            float4 wf0 = *(const float4*)&Ws[buf][kk][tx * 8];
            float4 wf1 = *(const float4*)&Ws[buf][kk][tx * 8 + 4];
            float ar[8] = {af0.x, af0.y, af0.z, af0.w, af1.x, af1.y, af1.z, af1.w};
            float wr[8] = {wf0.x, wf0.y, wf0.z, wf0.w, wf1.x, wf1.y, wf1.z, wf1.w};
            #pragma unroll
            for (int i = 0; i < 8; i++)
                #pragma unroll
                for (int j = 0; j < 8; j++)
                    acc[i][j] += ar[i] * wr[j];
        }
        if (more) {
            buf ^= 1;
            As[buf][lk+0][lr]    = na0.x; As[buf][lk+1][lr]    = na0.y;
            As[buf][lk+2][lr]    = na0.z; As[buf][lk+3][lr]    = na0.w;
            As[buf][lk+0][lr+64] = na1.x; As[buf][lk+1][lr+64] = na1.y;
            As[buf][lk+2][lr+64] = na1.z; As[buf][lk+3][lr+64] = na1.w;
            Ws[buf][lk+0][lr]    = nw0.x; Ws[buf][lk+1][lr]    = nw0.y;
            Ws[buf][lk+2][lr]    = nw0.z; Ws[buf][lk+3][lr]    = nw0.w;
            Ws[buf][lk+0][lr+64] = nw1.x; Ws[buf][lk+1][lr+64] = nw1.y;
            Ws[buf][lk+2][lr+64] = nw1.z; Ws[buf][lk+3][lr+64] = nw1.w;
            __syncthreads();
        }
    }

    #pragma unroll
    for (int i = 0; i < 8; i++) {
        int m = m0 + ty * 8 + i;
        if (m >= M) continue;
        const float* per = nullptr;
        if (EPI == 1) per = d_pe + (size_t)(m % NEXT) * DM;
        if (EPI == 2) per = d_pe + (size_t)(m % PRED + 2) * DM;
        #pragma unroll
        for (int jj = 0; jj < 8; jj += 4) {
            int n = n0 + tx * 8 + jj;
            float4 v = make_float4(acc[i][jj], acc[i][jj+1], acc[i][jj+2], acc[i][jj+3]);
            if (EPI == 1) {
                float4 p = *(const float4*)(per + n);
                v.x += p.x; v.y += p.y; v.z += p.z; v.w += p.w;
            }
            if (EPI == 2) {
                float4 p = *(const float4*)(per + n);
                v.x += 2.f*p.x; v.y += 2.f*p.y; v.z += 2.f*p.z; v.w += 2.f*p.w;
            }
            *(float4*)&C[(size_t)m * ldc + n] = v;
        }
    }
}

// ---------------- small-N GEMM (64x64, 4x4/thread), fused epilogues -----------
// EPI: 3=exp(acc+aux[n])  4=acc*std[b,n]+mean[b,n]  0=none
template<int EPI>
__global__ void __launch_bounds__(256)
gemm_tn(const float* __restrict__ A, const float* __restrict__ W,
        float* __restrict__ C, const float* __restrict__ aux,
        int M, int N, int K, int lda, int ldw, int ldc,
        long sA, long sW, long sC) {
    int g = blockIdx.z;
    A += (long)g * sA; W += (long)g * sW; C += (long)g * sC;
    __shared__ __align__(16) float As[16][68];
    __shared__ __align__(16) float Ws[16][68];
    const int tid = threadIdx.x;
    const int tx = tid & 15, ty = tid >> 4;
    const int m0 = blockIdx.y * 64, n0 = blockIdx.x * 64;
    const int lrow = tid >> 2, lk4 = (tid & 3) * 4;
    float acc[4][4] = {};
    const int mg = m0 + lrow, ng = n0 + lrow;
    const bool nok = ng < N;
    const float* Aptr = A + (size_t)mg * lda + lk4;
    const float* Wptr = W + (size_t)(nok ? ng : 0) * ldw + lk4;

    for (int k0 = 0; k0 < K; k0 += 16) {
        float4 av = *(const float4*)(Aptr + k0);
        float4 wv = nok ? *(const float4*)(Wptr + k0) : make_float4(0.f,0.f,0.f,0.f);
        As[lk4 + 0][lrow] = av.x; As[lk4 + 1][lrow] = av.y;
        As[lk4 + 2][lrow] = av.z; As[lk4 + 3][lrow] = av.w;
        Ws[lk4 + 0][lrow] = wv.x; Ws[lk4 + 1][lrow] = wv.y;
        Ws[lk4 + 2][lrow] = wv.z; Ws[lk4 + 3][lrow] = wv.w;
        __syncthreads();
        #pragma unroll
        for (int kk = 0; kk < 16; kk++) {
            float4 a = *(const float4*)&As[kk][ty * 4];
            float4 w = *(const float4*)&Ws[kk][tx * 4];
            float ar[4] = {a.x, a.y, a.z, a.w};
            float wr[4] = {w.x, w.y, w.z, w.w};
            #pragma unroll
            for (int i = 0; i < 4; i++)
                #pragma unroll
                for (int j = 0; j < 4; j++)
                    acc[i][j] += ar[i] * wr[j];
        }
        __syncthreads();
    }

    #pragma unroll
    for (int i = 0; i < 4; i++) {
        int m = m0 + ty * 4 + i;
        if (m >= M) continue;
        #pragma unroll
        for (int j = 0; j < 4; j++) {
            int n = n0 + tx * 4 + j;
            if (n >= N) continue;
            float v = acc[i][j];
            if (EPI == 3) v = expf(v + aux[n]);
            if (EPI == 4) {
                int b = m / PRED;
                v = v * d_std[b * CIN + n] + d_mean[b * CIN + n];
            }
            C[(size_t)m * ldc + n] = v;
        }
    }
}

// ---------------- 5: depthwise conv + SiLU, block per (g,b,p), reg history ----
__global__ void __launch_bounds__(256)
conv_silu_kernel(const float* __restrict__ cw, const float* __restrict__ cb) {
    int gid = blockIdx.x;
    int g   = gid / (BB * 6);
    int row = gid % (BB * 6);
    int tok0 = (row / 6) * PRED + (row % 6) * PATCH;
    int e = threadIdx.x;
    float w0 = cw[(g * DIN + e) * 4 + 0];
    float w1 = cw[(g * DIN + e) * 4 + 1];
    float w2 = cw[(g * DIN + e) * 4 + 2];
    float w3 = cw[(g * DIN + e) * 4 + 3];
    float bv = cb[g * DIN + e];
    float h0 = 0.f, h1 = 0.f, h2 = 0.f;
    const float* src = d_xz + (size_t)tok0 * 2048 + g * 512 + e;
    float* dst = d_xconv + (size_t)g * NTOK * DIN + (size_t)tok0 * DIN + e;
    #pragma unroll
    for (int t = 0; t < PATCH; t++) {
        float xv = src[(size_t)t * 2048];
        float acc = bv + w0 * h0 + w1 * h1 + w2 * h2 + w3 * xv;
        h0 = h1; h1 = h2; h2 = xv;
        float sig = 1.0f / (1.0f + expf(-acc));
        dst[(size_t)t * DIN] = acc * sig;
    }
}

// ---------------- 7: selective scan with fused dt, block per (g,b,p) ----------
__global__ void __launch_bounds__(256)
scan_kernel(const float* __restrict__ A_log, const float* __restrict__ Dp,
            const float* __restrict__ dtw, const float* __restrict__ dtb) {
    int gid = blockIdx.x;
    int g   = gid / (BB * 6);
    int row = gid % (BB * 6);
    int tok0 = (row / 6) * PRED + (row % 6) * PATCH;
    int e = threadIdx.x;

    float Av[NST];
    #pragma unroll
    for (int n = 0; n < NST; n++) Av[n] = -expf(A_log[((size_t)g * DIN + e) * NST + n]);
    float Dv = Dp[g * DIN + e];
    float dtbv = dtb[g * DIN + e];
    float4 dw0 = *(const float4*)(dtw + (size_t)(g * DIN + e) * DTR);
    float4 dw1 = *(const float4*)(dtw + (size_t)(g * DIN + e) * DTR + 4);
    float h[NST];
    #pragma unroll
    for (int n = 0; n < NST; n++) h[n] = 0.f;

    __shared__ float sh[40];
    for (int t = 0; t < PATCH; t++) {
        int tok = tok0 + t;
        if (e < 40) sh[e] = d_dbl[((size_t)g * NTOK + tok) * 40 + e];
        __syncthreads();

        float dtv = dtbv
            + sh[0]*dw0.x + sh[1]*dw0.y + sh[2]*dw0.z + sh[3]*dw0.w
            + sh[4]*dw1.x + sh[5]*dw1.y + sh[6]*dw1.z + sh[7]*dw1.w;
        dtv = (dtv > 20.f) ? dtv : log1pf(expf(dtv));

        size_t cidx = (size_t)g * NTOK * DIN + (size_t)tok * DIN + e;
        float xv = d_xconv[cidx];
        float dx = dtv * xv;
        float y = 0.f;
        #pragma unroll
        for (int n = 0; n < NST; n++) {
            h[n] = __expf(dtv * Av[n]) * h[n] + dx * sh[8 + n];
            y += h[n] * sh[24 + n];
        }
        y += Dv * xv;
        float zv = d_xz[(size_t)tok * 2048 + g * 512 + 256 + e];
        y *= zv / (1.0f + expf(-zv));
        d_y[cidx] = y;
        __syncthreads();
    }
}

// ---------------- host launcher ----------------
extern "C" void kernel_launch(void* const* d_in, const int* in_sizes, int n_in,
                              void* d_out, int out_size) {
    const float* x_enc     = (const float*)d_in[0];
    const float* x_mark    = (const float*)d_in[1];
    const float* conv_w    = (const float*)d_in[4];
    const float* temp_w    = (const float*)d_in[5];
    const float* hetero_w  = (const float*)d_in[6];
    const float* hetero_b  = (const float*)d_in[7];
    const float* in_proj_w = (const float*)d_in[8];
    const float* conv1_w   = (const float*)d_in[9];
    const float* conv1_b   = (const float*)d_in[10];
    const float* x_proj_w  = (const float*)d_in[11];
    const float* dt_proj_w = (const float*)d_in[12];
    const float* dt_proj_b = (const float*)d_in[13];
    const float* A_log     = (const float*)d_in[14];
    const float* D_param   = (const float*)d_in[15];
    const float* out_pw    = (const float*)d_in[16];
    const float* out_w     = (const float*)d_in[17];
    float* out = (float*)d_out;

    float *p_A1, *p_e1, *p_A2, *p_xc, *p_xz, *p_xconv, *p_dbl, *p_y, *p_xm, *p_scale, *p_We;
    cudaGetSymbolAddress((void**)&p_A1,    d_A1);
    cudaGetSymbolAddress((void**)&p_e1,    d_e1);
    cudaGetSymbolAddress((void**)&p_A2,    d_A2);
    cudaGetSymbolAddress((void**)&p_xc,    d_xc);
    cudaGetSymbolAddress((void**)&p_xz,    d_xz);
    cudaGetSymbolAddress((void**)&p_xconv, d_xconv);
    cudaGetSymbolAddress((void**)&p_dbl,   d_dbl);
    cudaGetSymbolAddress((void**)&p_y,     d_y);
    cudaGetSymbolAddress((void**)&p_xm,    d_xm);
    cudaGetSymbolAddress((void**)&p_scale, d_scale);
    cudaGetSymbolAddress((void**)&p_We,    d_We);

    stats_kernel<<<BB * CIN, 256>>>(x_enc);
    prep_kernel<<<((KE + NEXT) * DM + 255) / 256, 256>>>(conv_w, temp_w);
    inv1_kernel<<<BB * NEXT, 128>>>(x_enc, x_mark);
    // e1 = A1 @ We^T (+pe): M=3136, N=512, K=112
    gemm128<1><<<dim3(4, 25, 1), 256>>>(p_A1, p_We, p_e1,
                                        BB*NEXT, DM, KE, KE, KE, DM, 0, 0, 0);
    // scale = exp(e1 @ hetero_w^T + hb): M=3136, N=32, K=512
    gemm_tn<3><<<dim3(1, 49, 1), 256>>>(p_e1, hetero_w, p_scale, hetero_b,
                                        BB*NEXT, CIN, DM, DM, DM, CIN, 0, 0, 0);
    inv2_kernel<<<NTOK, 128>>>(x_enc, x_mark);
    // xc = A2 @ We^T (+2*pe): M=3072, N=512, K=112
    gemm128<2><<<dim3(4, 24, 1), 256>>>(p_A2, p_We, p_xc,
                                        NTOK, DM, KE, KE, KE, DM, 0, 0, 0);
    // in_proj batched: (3072 x 512) = (3072 x 128) @ (512 x 128)^T per group
    gemm128<0><<<dim3(4, 24, GG), 256>>>(p_xc, in_proj_w, p_xz,
                                         NTOK, 512, DG, DM, DG, 2048,
                                         DG, (long)512 * DG, 512);
    conv_silu_kernel<<<GG * BB * 6, 256>>>(conv1_w, conv1_b);
    // x_proj batched: (3072 x 40) = (3072 x 256) @ (40 x 256)^T per group
    gemm_tn<0><<<dim3(1, 48, GG), 256>>>(p_xconv, x_proj_w, p_dbl, nullptr,
                                         NTOK, 40, DIN, DIN, DIN, 40,
                                         (long)NTOK * DIN, 40L * DIN, (long)NTOK * 40);
    scan_kernel<<<GG * BB * 6, 256>>>(A_log, D_param, dt_proj_w, dt_proj_b);
    // out_proj batched: (3072 x 128) = (3072 x 256) @ (128 x 256)^T per group
    gemm128<0><<<dim3(1, 24, GG), 256>>>(p_y, out_pw, p_xm,
                                         NTOK, DG, DIN, DIN, DIN, DM,
                                         (long)NTOK * DIN, (long)DG * DIN, DG);
    // final: out = (xm @ out_w^T) * std + mean : M=3072, N=32, K=512
    gemm_tn<4><<<dim3(1, 48, 1), 256>>>(p_xm, out_w, out, nullptr,
                                        NTOK, CIN, DM, DM, DM, CIN, 0, 0, 0);
}

// round 4
// speedup vs baseline: 1.2010x; 1.2010x over previous
#include <cuda_runtime.h>
#include <cuda_bf16.h>
#include <math.h>
#include <stdint.h>

// ---------------- problem constants ----------------
#define BB    32
#define LL    1024
#define CIN   32
#define DM    512
#define NMARK 4
#define GG    4
#define DG    128
#define DIN   256
#define NST   16
#define DTR   8
#define PATCH 16
#define PRED  96
#define NTOK  (BB*PRED)      // 3072 tokens actually needed
#define NEXT  98             // extended token set per batch: l=0 and l=927..1023
#define KE    112            // embed K padded to multiple of 16 (100 -> 112)
#define LN1E4 9.210340371976184f

// ---------------- scratch (static __device__, no allocs) ----------------
__device__ float d_mean [BB*CIN];
__device__ float d_std  [BB*CIN];
__device__ float d_We   [DM*KE];               // fused embed weight, [DM][KE] (cols 100..111 zero)
__device__ float d_pe   [NEXT*DM];             // positional embeds for the 98 needed l values
__device__ float d_A1   [BB*NEXT*KE];          // embed input rows for e1/scale
__device__ float d_e1   [BB*NEXT*DM];
__device__ float d_scale[BB*NEXT*CIN];
__device__ float d_A2   [NTOK*KE];             // embed input rows for xc
__device__ float d_xc   [NTOK*DM];
__device__ float d_xz   [NTOK*2048];           // in_proj output (per group: xc|z)
__device__ float d_xconv[GG*NTOK*DIN];         // silu(depthwise conv)
__device__ float d_dbl  [GG*NTOK*40];          // x_proj output (dt_raw|B|C)
__device__ float d_y    [GG*NTOK*DIN];         // scan output * silu(z)
__device__ float d_xm   [NTOK*DM];             // out_proj output

// ---------------- 1: per-(b,c) mean/std over L ----------------
__global__ void stats_kernel(const float* __restrict__ x_enc) {
    int bc = blockIdx.x;                       // b*32 + c
    const float* xp = x_enc + (size_t)(bc >> 5) * (LL*CIN) + (bc & 31);
    float s = 0.f, sq = 0.f;
    for (int l = threadIdx.x; l < LL; l += 256) {
        float v = xp[(size_t)l * CIN];
        s += v; sq += v * v;
    }
    __shared__ float sh[512];
    sh[threadIdx.x] = s; sh[256 + threadIdx.x] = sq;
    __syncthreads();
    for (int st = 128; st; st >>= 1) {
        if (threadIdx.x < st) {
            sh[threadIdx.x]       += sh[threadIdx.x + st];
            sh[256 + threadIdx.x] += sh[256 + threadIdx.x + st];
        }
        __syncthreads();
    }
    if (threadIdx.x == 0) {
        float m   = sh[0]   * (1.f / LL);
        float var = sh[256] * (1.f / LL) - m * m;
        d_mean[bc] = m;
        d_std[bc]  = sqrtf(var + 1e-5f);
    }
}

// ---------------- 2: build We^T ([DM][KE], zero-padded) + pe table (98x512) ---
__global__ void prep_kernel(const float* __restrict__ conv_w,
                            const float* __restrict__ temp_w) {
    int idx = blockIdx.x * blockDim.x + threadIdx.x;
    if (idx < DM * KE) {
        int d = idx / KE, r = idx % KE;
        float v = 0.f;
        if (r < 96)       v = conv_w[d * 96 + (r & 31) * 3 + (r >> 5)];
        else if (r < 100) v = temp_w[d * 4 + (r - 96)];
        d_We[idx] = v;                          // d_We[d][r]
    } else if (idx < DM * KE + NEXT * DM) {
        int j = idx - DM * KE;
        int u = j / DM, d = j % DM;
        int l = (u == 0) ? 0 : (926 + u);
        float freq = expf(-(float)(d & ~1) * (LN1E4 / (float)DM));
        float arg  = (float)l * freq;
        d_pe[j] = (d & 1) ? cosf(arg) : sinf(arg);
    }
}

// ---------------- 3a: build A1 rows (normalized window + mark) ----------------
__global__ void inv1_kernel(const float* __restrict__ x_enc,
                            const float* __restrict__ mark) {
    int row = blockIdx.x;                      // b*NEXT + u
    int tid = threadIdx.x;
    if (tid >= KE) return;
    int u = row % NEXT, b = row / NEXT;
    int l  = (u == 0) ? 0 : (926 + u);
    int lp = (l == 0) ? (LL - 1) : (l - 1);
    int ln = (l == LL - 1) ? 0 : (l + 1);
    float v = 0.f;
    if (tid < 96) {
        int k = tid >> 5, c = tid & 31;
        int ll = (k == 0) ? lp : ((k == 1) ? l : ln);
        float x = x_enc[((size_t)b * LL + ll) * CIN + c];
        v = (x - d_mean[b * CIN + c]) / d_std[b * CIN + c];
    } else if (tid < 100) {
        v = mark[((size_t)b * LL + l) * NMARK + (tid - 96)];
    }
    d_A1[(size_t)row * KE + tid] = v;
}

// ---------------- 3b: build A2 rows (normalized*(1+scale) + 2*mark) -----------
__global__ void inv2_kernel(const float* __restrict__ x_enc,
                            const float* __restrict__ mark) {
    int row = blockIdx.x;                      // tok = b*96 + j
    int tid = threadIdx.x;
    if (tid >= KE) return;
    int b = row / PRED, j = row % PRED;
    int l  = 928 + j;
    int lp = l - 1;
    int ln = (l == LL - 1) ? 0 : (l + 1);
    float v = 0.f;
    if (tid < 96) {
        int k = tid >> 5, c = tid & 31;
        int ll = (k == 0) ? lp : ((k == 1) ? l : ln);
        int u  = (ll == 0) ? 0 : (ll - 926);
        float x  = x_enc[((size_t)b * LL + ll) * CIN + c];
        float xn = (x - d_mean[b * CIN + c]) / d_std[b * CIN + c];
        v = xn * (1.0f + d_scale[((size_t)b * NEXT + u) * CIN + c]);
    } else if (tid < 100) {
        v = 2.0f * mark[((size_t)b * LL + l) * NMARK + (tid - 96)];
    }
    d_A2[(size_t)row * KE + tid] = v;
}

// =====================================================================
// TF32 split-3 tensor-core GEMM: C[M,N] = A[M,K] @ W[N,K]^T
// 64x64 block tile, 128 threads (4 warps, 32x32 each), BK=16 double-buffered.
// Accuracy ~fp32 (hi*hi + hi*lo + lo*hi; missing lo*lo ~ 2^-24 rel).
// Requires: M%64==0, K%16==0, lda/ldw%4==0, N even. Ragged N (<64/tile) ok.
// EPI: 0=none  1=+pe[m%NEXT]  2=+2*pe[m%96+2]
// =====================================================================
__device__ __forceinline__ uint32_t f2tf32(float v) {
    uint32_t r; asm("cvt.rna.tf32.f32 %0, %1;" : "=r"(r) : "f"(v)); return r;
}
__device__ __forceinline__ void split_tf32(float v, uint32_t& hi, uint32_t& lo) {
    hi = f2tf32(v);
    lo = f2tf32(v - __uint_as_float(hi));
}
__device__ __forceinline__ void mma_tf32(float* d, const uint32_t* a, const uint32_t* b) {
    asm volatile("mma.sync.aligned.m16n8k8.row.col.f32.tf32.tf32.f32 "
        "{%0,%1,%2,%3},{%4,%5,%6,%7},{%8,%9},{%0,%1,%2,%3};"
        : "+f"(d[0]), "+f"(d[1]), "+f"(d[2]), "+f"(d[3])
        : "r"(a[0]), "r"(a[1]), "r"(a[2]), "r"(a[3]), "r"(b[0]), "r"(b[1]));
}

template<int EPI>
__global__ void __launch_bounds__(128)
gemm_mma(const float* __restrict__ A, const float* __restrict__ W,
         float* __restrict__ C, int M, int N, int K,
         int lda, int ldw, int ldc, long sA, long sW, long sC) {
    int g = blockIdx.z;
    A += (long)g * sA; W += (long)g * sW; C += (long)g * sC;

    __shared__ __align__(16) float As[2][64][20];
    __shared__ __align__(16) float Ws[2][64][20];

    const int tid = threadIdx.x;
    const int m0 = blockIdx.y * 64, n0 = blockIdx.x * 64;
    const int row = tid >> 1, kq = (tid & 1) * 8;
    const bool wok = (n0 + row) < N;
    const float* Ag = A + (size_t)(m0 + row) * lda + kq;
    const float* Wg = W + (size_t)(wok ? (n0 + row) : 0) * ldw + kq;
    const float4 z4 = make_float4(0.f, 0.f, 0.f, 0.f);

    // preload k-tile 0
    {
        float4 a0 = *(const float4*)Ag;
        float4 a1 = *(const float4*)(Ag + 4);
        float4 w0 = wok ? *(const float4*)Wg : z4;
        float4 w1 = wok ? *(const float4*)(Wg + 4) : z4;
        *(float4*)&As[0][row][kq]     = a0; *(float4*)&As[0][row][kq + 4] = a1;
        *(float4*)&Ws[0][row][kq]     = w0; *(float4*)&Ws[0][row][kq + 4] = w1;
    }
    __syncthreads();

    const int lane = tid & 31, grp = lane >> 2, tig = lane & 3;
    const int wid = tid >> 5;
    const int mbase = (wid >> 1) * 32, nbase = (wid & 1) * 32;

    float acc[2][4][4] = {};
    int buf = 0;
    float4 pa0, pa1, pw0, pw1;

    for (int k0 = 0; k0 < K; k0 += 16) {
        const bool more = (k0 + 16) < K;
        if (more) {
            pa0 = *(const float4*)(Ag + k0 + 16);
            pa1 = *(const float4*)(Ag + k0 + 20);
            pw0 = wok ? *(const float4*)(Wg + k0 + 16) : z4;
            pw1 = wok ? *(const float4*)(Wg + k0 + 20) : z4;
        }
        #pragma unroll
        for (int ks = 0; ks < 2; ks++) {
            const int kb = ks * 8 + tig;
            uint32_t Ahi[2][4], Alo[2][4], Bhi[4][2], Blo[4][2];
            #pragma unroll
            for (int mt = 0; mt < 2; mt++) {
                int mr = mbase + mt * 16 + grp;
                split_tf32(As[buf][mr][kb],         Ahi[mt][0], Alo[mt][0]);
                split_tf32(As[buf][mr + 8][kb],     Ahi[mt][1], Alo[mt][1]);
                split_tf32(As[buf][mr][kb + 4],     Ahi[mt][2], Alo[mt][2]);
                split_tf32(As[buf][mr + 8][kb + 4], Ahi[mt][3], Alo[mt][3]);
            }
            #pragma unroll
            for (int nt = 0; nt < 4; nt++) {
                int nc = nbase + nt * 8 + grp;
                split_tf32(Ws[buf][nc][kb],     Bhi[nt][0], Blo[nt][0]);
                split_tf32(Ws[buf][nc][kb + 4], Bhi[nt][1], Blo[nt][1]);
            }
            #pragma unroll
            for (int mt = 0; mt < 2; mt++)
                #pragma unroll
                for (int nt = 0; nt < 4; nt++) {
                    mma_tf32(acc[mt][nt], Ahi[mt], Bhi[nt]);
                    mma_tf32(acc[mt][nt], Ahi[mt], Blo[nt]);
                    mma_tf32(acc[mt][nt], Alo[mt], Bhi[nt]);
                }
        }
        if (more) {
            buf ^= 1;
            *(float4*)&As[buf][row][kq]     = pa0; *(float4*)&As[buf][row][kq + 4] = pa1;
            *(float4*)&Ws[buf][row][kq]     = pw0; *(float4*)&Ws[buf][row][kq + 4] = pw1;
            __syncthreads();
        }
    }

    // epilogue: c0,c1 -> (grp, tig*2, +1); c2,c3 -> (grp+8, ...)
    #pragma unroll
    for (int mt = 0; mt < 2; mt++) {
        #pragma unroll
        for (int half = 0; half < 2; half++) {
            int m = m0 + mbase + mt * 16 + grp + half * 8;
            if (m >= M) continue;
            const float* per = nullptr;
            if (EPI == 1) per = d_pe + (size_t)(m % NEXT) * DM;
            if (EPI == 2) per = d_pe + (size_t)(m % PRED + 2) * DM;
            #pragma unroll
            for (int nt = 0; nt < 4; nt++) {
                int n = n0 + nbase + nt * 8 + tig * 2;
                if (n >= N) continue;          // N even, pair in/out together
                float v0 = acc[mt][nt][half * 2 + 0];
                float v1 = acc[mt][nt][half * 2 + 1];
                if (EPI == 1) { v0 += per[n];       v1 += per[n + 1]; }
                if (EPI == 2) { v0 += 2.f * per[n]; v1 += 2.f * per[n + 1]; }
                *(float2*)&C[(size_t)m * ldc + n] = make_float2(v0, v1);
            }
        }
    }
}

// ---------------- small-N fp32 GEMM (64x64, 4x4/thread), fused epilogues ------
// EPI: 3=exp(acc+aux[n])  4=acc*std[b,n]+mean[b,n]
template<int EPI>
__global__ void __launch_bounds__(256)
gemm_tn(const float* __restrict__ A, const float* __restrict__ W,
        float* __restrict__ C, const float* __restrict__ aux,
        int M, int N, int K, int lda, int ldw, int ldc) {
    __shared__ __align__(16) float As[16][68];
    __shared__ __align__(16) float Ws[16][68];
    const int tid = threadIdx.x;
    const int tx = tid & 15, ty = tid >> 4;
    const int m0 = blockIdx.y * 64, n0 = blockIdx.x * 64;
    const int lrow = tid >> 2, lk4 = (tid & 3) * 4;
    float acc[4][4] = {};
    const int mg = m0 + lrow, ng = n0 + lrow;
    const bool nok = ng < N;
    const float* Aptr = A + (size_t)mg * lda + lk4;
    const float* Wptr = W + (size_t)(nok ? ng : 0) * ldw + lk4;

    for (int k0 = 0; k0 < K; k0 += 16) {
        float4 av = *(const float4*)(Aptr + k0);
        float4 wv = nok ? *(const float4*)(Wptr + k0) : make_float4(0.f,0.f,0.f,0.f);
        As[lk4 + 0][lrow] = av.x; As[lk4 + 1][lrow] = av.y;
        As[lk4 + 2][lrow] = av.z; As[lk4 + 3][lrow] = av.w;
        Ws[lk4 + 0][lrow] = wv.x; Ws[lk4 + 1][lrow] = wv.y;
        Ws[lk4 + 2][lrow] = wv.z; Ws[lk4 + 3][lrow] = wv.w;
        __syncthreads();
        #pragma unroll
        for (int kk = 0; kk < 16; kk++) {
            float4 a = *(const float4*)&As[kk][ty * 4];
            float4 w = *(const float4*)&Ws[kk][tx * 4];
            float ar[4] = {a.x, a.y, a.z, a.w};
            float wr[4] = {w.x, w.y, w.z, w.w};
            #pragma unroll
            for (int i = 0; i < 4; i++)
                #pragma unroll
                for (int j = 0; j < 4; j++)
                    acc[i][j] += ar[i] * wr[j];
        }
        __syncthreads();
    }

    #pragma unroll
    for (int i = 0; i < 4; i++) {
        int m = m0 + ty * 4 + i;
        if (m >= M) continue;
        #pragma unroll
        for (int j = 0; j < 4; j++) {
            int n = n0 + tx * 4 + j;
            if (n >= N) continue;
            float v = acc[i][j];
            if (EPI == 3) v = expf(v + aux[n]);
            if (EPI == 4) {
                int b = m / PRED;
                v = v * d_std[b * CIN + n] + d_mean[b * CIN + n];
            }
            C[(size_t)m * ldc + n] = v;
        }
    }
}

// ---------------- 5: depthwise conv + SiLU, block per (g,b,p), reg history ----
__global__ void __launch_bounds__(256)
conv_silu_kernel(const float* __restrict__ cw, const float* __restrict__ cb) {
    int gid = blockIdx.x;
    int g   = gid / (BB * 6);
    int row = gid % (BB * 6);
    int tok0 = (row / 6) * PRED + (row % 6) * PATCH;
    int e = threadIdx.x;
    float w0 = cw[(g * DIN + e) * 4 + 0];
    float w1 = cw[(g * DIN + e) * 4 + 1];
    float w2 = cw[(g * DIN + e) * 4 + 2];
    float w3 = cw[(g * DIN + e) * 4 + 3];
    float bv = cb[g * DIN + e];
    float h0 = 0.f, h1 = 0.f, h2 = 0.f;
    const float* src = d_xz + (size_t)tok0 * 2048 + g * 512 + e;
    float* dst = d_xconv + (size_t)g * NTOK * DIN + (size_t)tok0 * DIN + e;
    #pragma unroll
    for (int t = 0; t < PATCH; t++) {
        float xv = src[(size_t)t * 2048];
        float acc = bv + w0 * h0 + w1 * h1 + w2 * h2 + w3 * xv;
        h0 = h1; h1 = h2; h2 = xv;
        float sig = 1.0f / (1.0f + expf(-acc));
        dst[(size_t)t * DIN] = acc * sig;
    }
}

// ---------------- 7: selective scan with fused dt, block per (g,b,p) ----------
__global__ void __launch_bounds__(256)
scan_kernel(const float* __restrict__ A_log, const float* __restrict__ Dp,
            const float* __restrict__ dtw, const float* __restrict__ dtb) {
    int gid = blockIdx.x;
    int g   = gid / (BB * 6);
    int row = gid % (BB * 6);
    int tok0 = (row / 6) * PRED + (row % 6) * PATCH;
    int e = threadIdx.x;

    float Av[NST];
    #pragma unroll
    for (int n = 0; n < NST; n++) Av[n] = -expf(A_log[((size_t)g * DIN + e) * NST + n]);
    float Dv = Dp[g * DIN + e];
    float dtbv = dtb[g * DIN + e];
    float4 dw0 = *(const float4*)(dtw + (size_t)(g * DIN + e) * DTR);
    float4 dw1 = *(const float4*)(dtw + (size_t)(g * DIN + e) * DTR + 4);
    float h[NST];
    #pragma unroll
    for (int n = 0; n < NST; n++) h[n] = 0.f;

    __shared__ float sh[40];
    for (int t = 0; t < PATCH; t++) {
        int tok = tok0 + t;
        if (e < 40) sh[e] = d_dbl[((size_t)g * NTOK + tok) * 40 + e];
        __syncthreads();

        float dtv = dtbv
            + sh[0]*dw0.x + sh[1]*dw0.y + sh[2]*dw0.z + sh[3]*dw0.w
            + sh[4]*dw1.x + sh[5]*dw1.y + sh[6]*dw1.z + sh[7]*dw1.w;
        dtv = (dtv > 20.f) ? dtv : log1pf(expf(dtv));

        size_t cidx = (size_t)g * NTOK * DIN + (size_t)tok * DIN + e;
        float xv = d_xconv[cidx];
        float dx = dtv * xv;
        float y = 0.f;
        #pragma unroll
        for (int n = 0; n < NST; n++) {
            h[n] = __expf(dtv * Av[n]) * h[n] + dx * sh[8 + n];
            y += h[n] * sh[24 + n];
        }
        y += Dv * xv;
        float zv = d_xz[(size_t)tok * 2048 + g * 512 + 256 + e];
        y *= zv / (1.0f + expf(-zv));
        d_y[cidx] = y;
        __syncthreads();
    }
}

// ---------------- host launcher ----------------
extern "C" void kernel_launch(void* const* d_in, const int* in_sizes, int n_in,
                              void* d_out, int out_size) {
    const float* x_enc     = (const float*)d_in[0];
    const float* x_mark    = (const float*)d_in[1];
    const float* conv_w    = (const float*)d_in[4];
    const float* temp_w    = (const float*)d_in[5];
    const float* hetero_w  = (const float*)d_in[6];
    const float* hetero_b  = (const float*)d_in[7];
    const float* in_proj_w = (const float*)d_in[8];
    const float* conv1_w   = (const float*)d_in[9];
    const float* conv1_b   = (const float*)d_in[10];
    const float* x_proj_w  = (const float*)d_in[11];
    const float* dt_proj_w = (const float*)d_in[12];
    const float* dt_proj_b = (const float*)d_in[13];
    const float* A_log     = (const float*)d_in[14];
    const float* D_param   = (const float*)d_in[15];
    const float* out_pw    = (const float*)d_in[16];
    const float* out_w     = (const float*)d_in[17];
    float* out = (float*)d_out;

    float *p_A1, *p_e1, *p_A2, *p_xc, *p_xz, *p_xconv, *p_dbl, *p_y, *p_xm, *p_scale, *p_We;
    cudaGetSymbolAddress((void**)&p_A1,    d_A1);
    cudaGetSymbolAddress((void**)&p_e1,    d_e1);
    cudaGetSymbolAddress((void**)&p_A2,    d_A2);
    cudaGetSymbolAddress((void**)&p_xc,    d_xc);
    cudaGetSymbolAddress((void**)&p_xz,    d_xz);
    cudaGetSymbolAddress((void**)&p_xconv, d_xconv);
    cudaGetSymbolAddress((void**)&p_dbl,   d_dbl);
    cudaGetSymbolAddress((void**)&p_y,     d_y);
    cudaGetSymbolAddress((void**)&p_xm,    d_xm);
    cudaGetSymbolAddress((void**)&p_scale, d_scale);
    cudaGetSymbolAddress((void**)&p_We,    d_We);

    stats_kernel<<<BB * CIN, 256>>>(x_enc);
    prep_kernel<<<((KE + NEXT) * DM + 255) / 256, 256>>>(conv_w, temp_w);
    inv1_kernel<<<BB * NEXT, 128>>>(x_enc, x_mark);
    // e1 = A1 @ We^T (+pe): M=3136, N=512, K=112   [tensor]
    gemm_mma<1><<<dim3(8, 49), 128>>>(p_A1, p_We, p_e1,
                                      BB*NEXT, DM, KE, KE, KE, DM, 0, 0, 0);
    // scale = exp(e1 @ hetero_w^T + hb): M=3136, N=32, K=512   [fp32]
    gemm_tn<3><<<dim3(1, 49), 256>>>(p_e1, hetero_w, p_scale, hetero_b,
                                     BB*NEXT, CIN, DM, DM, DM, CIN);
    inv2_kernel<<<NTOK, 128>>>(x_enc, x_mark);
    // xc = A2 @ We^T (+2*pe): M=3072, N=512, K=112   [tensor]
    gemm_mma<2><<<dim3(8, 48), 128>>>(p_A2, p_We, p_xc,
                                      NTOK, DM, KE, KE, KE, DM, 0, 0, 0);
    // in_proj batched: (3072 x 512) = (3072 x 128) @ (512 x 128)^T   [tensor]
    gemm_mma<0><<<dim3(8, 48, GG), 128>>>(p_xc, in_proj_w, p_xz,
                                          NTOK, 512, DG, DM, DG, 2048,
                                          DG, (long)512 * DG, 512);
    conv_silu_kernel<<<GG * BB * 6, 256>>>(conv1_w, conv1_b);
    // x_proj batched: (3072 x 40) = (3072 x 256) @ (40 x 256)^T   [tensor]
    gemm_mma<0><<<dim3(1, 48, GG), 128>>>(p_xconv, x_proj_w, p_dbl,
                                          NTOK, 40, DIN, DIN, DIN, 40,
                                          (long)NTOK * DIN, 40L * DIN, (long)NTOK * 40);
    scan_kernel<<<GG * BB * 6, 256>>>(A_log, D_param, dt_proj_w, dt_proj_b);
    // out_proj batched: (3072 x 128) = (3072 x 256) @ (128 x 256)^T   [tensor]
    gemm_mma<0><<<dim3(2, 48, GG), 128>>>(p_y, out_pw, p_xm,
                                          NTOK, DG, DIN, DIN, DIN, DM,
                                          (long)NTOK * DIN, (long)DG * DIN, DG);
    // final: out = (xm @ out_w^T) * std + mean : M=3072, N=32, K=512   [fp32]
    gemm_tn<4><<<dim3(1, 48), 256>>>(p_xm, out_w, out, nullptr,
                                     NTOK, CIN, DM, DM, DM, CIN);
}